// round 16
// baseline (speedup 1.0000x reference)
#include <cuda_runtime.h>
#include <cstdint>

#define NTOK 65536
#define NTILE 1024             // 64-token tiles
#define OUT_ANG 0
#define OUT_UN  (NTOK*14)
#define OUT_POS (2*NTOK*14)
#define OUT_ATG (2*NTOK*14 + NTOK*42)

#define QMAX 32512.f           // 256*127
#define XQS 36                 // row stride in uint2 {h word, l word}
#define LAYER_U2 (128 * XQS)   // 4608 uint2 per W layer image (36864 B)

// smem byte offsets (double-buffered W)
#define SM_W0   0              // 36864 B
#define SM_W1   36864          // 36864 B
#define SM_X    73728          // 18432 B
#define SM_SB   92160          // 3072 B
#define SM_BIAS 95232          // 2560 B
#define SM_SROW 97792          // 512 B
#define SM_INV  98304          // 256 B
#define SM_RMP  98560          // 1024 B
#define SM_UNB  99584          // 3584 B  (unnorm; reused in-place for angles)
#define SM_OWS  103168         // 7168 B  (head weights, staged once)
#define SM_TOT  110336
// post-final-gemm aliases inside the b1 region (free after L5 gemm):
#define FS_STRIDE 129          // Fs 64x129 fp32 @ SM_W1 (33024 B)
// saf 64x8x12 fp32 = 24576 B @ SM_W1 (after head consumes Fs)

__device__ uint2 wqbuf[6 * LAYER_U2];
__device__ float sbg[6 * 128];

__device__ __forceinline__ void mma_s8(int c[4], uint32_t a0, uint32_t a1,
                                       uint32_t a2, uint32_t a3,
                                       uint32_t b0, uint32_t b1) {
    asm("mma.sync.aligned.m16n8k32.row.col.s32.s8.s8.s32 "
        "{%0,%1,%2,%3}, {%4,%5,%6,%7}, {%8,%9}, {%0,%1,%2,%3};"
        : "+r"(c[0]), "+r"(c[1]), "+r"(c[2]), "+r"(c[3])
        : "r"(a0), "r"(a1), "r"(a2), "r"(a3), "r"(b0), "r"(b1));
}

__device__ __forceinline__ void split4(const int q[4], uint32_t& hw, uint32_t& lw) {
    uint32_t a = 0, b = 0;
#pragma unroll
    for (int i = 0; i < 4; i++) {
        int h = (q[i] + 128) >> 8;
        int l = q[i] - (h << 8);
        a |= (uint32_t)(h & 0xFF) << (8 * i);
        b |= (uint32_t)(l & 0xFF) << (8 * i);
    }
    hw = a; lw = b;
}

__device__ __forceinline__ uint32_t smem_u32(const void* p) {
    uint32_t a; asm("{ .reg .u64 t; cvta.to.shared.u64 t, %1; cvt.u32.u64 %0, t; }" : "=r"(a) : "l"(p));
    return a;
}
#define CP_COMMIT() asm volatile("cp.async.commit_group;" ::: "memory")
#define CP_WAIT(n)  asm volatile("cp.async.wait_group %0;" :: "n"(n) : "memory")

__device__ __forceinline__ void copyW_async(uint32_t dst_s, int layer, int tid) {
    const char* src = (const char*)(wqbuf + (size_t)layer * LAYER_U2);
#pragma unroll
    for (int i = 0; i < 9; i++) {
        uint32_t d = dst_s + (uint32_t)(tid + i * 256) * 16u;
        asm volatile("cp.async.cg.shared.global [%0], [%1], 16;"
                     :: "r"(d), "l"(src + (size_t)(tid + i * 256) * 16) : "memory");
    }
}

// ---------------------------------------------------------------------------
// merged prep: 768 blocks x 32 threads; block = (layer, n) column
// layer order: 0=Wa 1=Wi 2=w1[0] 3=w2[0] 4=w1[1] 5=w2[1]
// ---------------------------------------------------------------------------
__device__ __forceinline__ const float* layer_src(int layer,
    const float* Wa, const float* Wi, const float* w1, const float* w2) {
    switch (layer) {
        case 0: return Wa; case 1: return Wi; case 2: return w1;
        case 3: return w2; case 4: return w1 + 16384; default: return w2 + 16384;
    }
}

__global__ void prep(const float* __restrict__ Wa, const float* __restrict__ Wi,
                     const float* __restrict__ w1, const float* __restrict__ w2) {
    int wgl = blockIdx.x;                    // 0..767
    int layer = wgl >> 7, n = wgl & 127;
    int l = threadIdx.x;                     // word index 0..31
    const float* src = layer_src(layer, Wa, Wi, w1, w2);
    float v[4];
#pragma unroll
    for (int i = 0; i < 4; i++) v[i] = src[(l * 4 + i) * 128 + n];
    float m = fmaxf(fmaxf(fabsf(v[0]), fabsf(v[1])), fmaxf(fabsf(v[2]), fabsf(v[3])));
#pragma unroll
    for (int off = 16; off >= 1; off >>= 1)
        m = fmaxf(m, __shfl_xor_sync(0xFFFFFFFFu, m, off));
    m = fmaxf(m, 1e-20f);
    float scale = m * (1.f / QMAX);
    if (l == 0) sbg[wgl] = scale;
    float inv = QMAX / m;
    int q[4];
#pragma unroll
    for (int i = 0; i < 4; i++) q[i] = __float2int_rn(v[i] * inv);
    uint32_t hw, lw;
    split4(q, hw, lw);
    wqbuf[(size_t)layer * LAYER_U2 + n * XQS + l] = make_uint2(hw, lw);
}

// ---------------------------------------------------------------------------
// persistent fused MLP + frames kernel: 64 tokens/tile, 256 threads, 2 CTAs/SM
// ---------------------------------------------------------------------------

__device__ __forceinline__ void stageX_quant(uint2* __restrict__ Xq,
                                             const float* __restrict__ g,
                                             int tokBase, int tid,
                                             float* __restrict__ srow_out) {
    int w = tid >> 5, l = tid & 31;
    const float4* src = (const float4*)g;
#pragma unroll
    for (int i = 0; i < 8; i++) {
        int row = w + 8 * i;
        float4 v = src[(size_t)(tokBase + row) * 32 + l];
        float r0 = fmaxf(v.x, 0.f), r1 = fmaxf(v.y, 0.f);
        float r2 = fmaxf(v.z, 0.f), r3 = fmaxf(v.w, 0.f);
        float lm = fmaxf(fmaxf(r0, r1), fmaxf(r2, r3));
#pragma unroll
        for (int off = 16; off >= 1; off >>= 1)
            lm = fmaxf(lm, __shfl_xor_sync(0xFFFFFFFFu, lm, off));
        lm = fmaxf(lm, 1e-20f);
        float inv = QMAX / lm;
        if (l == 0) srow_out[row] = lm * (1.f / QMAX);
        int q[4] = { __float2int_rn(r0 * inv), __float2int_rn(r1 * inv),
                     __float2int_rn(r2 * inv), __float2int_rn(r3 * inv) };
        uint32_t hw, lw;
        split4(q, hw, lw);
        Xq[row * XQS + l] = make_uint2(hw, lw);
    }
}

__device__ __forceinline__ void zeroP(int P1[2][4][4], int P23[2][4][4]) {
#pragma unroll
    for (int mt = 0; mt < 2; mt++)
#pragma unroll
        for (int nt = 0; nt < 4; nt++)
#pragma unroll
            for (int d = 0; d < 4; d++) { P1[mt][nt][d] = 0; P23[mt][nt][d] = 0; }
}

__device__ __forceinline__ void gemm(const uint2* __restrict__ Wq,
                                     const uint2* __restrict__ Xq,
                                     int P1[2][4][4], int P23[2][4][4],
                                     int wm, int wn, int lane) {
    const int lq = lane & 3, lr = lane >> 2;
#pragma unroll
    for (int kk = 0; kk < 4; kk++) {
        const int p0 = kk * 8 + lq;
        const int p1 = p0 + 4;
        uint32_t a1[2][4], a2[2][4];
#pragma unroll
        for (int mt = 0; mt < 2; mt++) {
            int r = (wm * 32 + mt * 16 + lr) * XQS;
            uint2 v0 = Xq[r + p0];
            uint2 v1 = Xq[r + 8 * XQS + p0];
            uint2 v2 = Xq[r + p1];
            uint2 v3 = Xq[r + 8 * XQS + p1];
            a1[mt][0] = v0.x; a2[mt][0] = v0.y;
            a1[mt][1] = v1.x; a2[mt][1] = v1.y;
            a1[mt][2] = v2.x; a2[mt][2] = v2.y;
            a1[mt][3] = v3.x; a2[mt][3] = v3.y;
        }
#pragma unroll
        for (int nt = 0; nt < 4; nt++) {
            int n = (wn * 32 + nt * 8 + lr) * XQS;
            uint2 b0 = Wq[n + p0];
            uint2 b1 = Wq[n + p1];
#pragma unroll
            for (int mt = 0; mt < 2; mt++) {
                mma_s8(P1[mt][nt],  a1[mt][0], a1[mt][1], a1[mt][2], a1[mt][3], b0.x, b1.x);
                mma_s8(P23[mt][nt], a1[mt][0], a1[mt][1], a1[mt][2], a1[mt][3], b0.y, b1.y);
                mma_s8(P23[mt][nt], a2[mt][0], a2[mt][1], a2[mt][2], a2[mt][3], b0.x, b1.x);
            }
        }
    }
}

#define DEQ_VAL(mt, nt, d, r, c) \
    (fmaf(65536.f, (float)P1[mt][nt][d], 256.f * (float)P23[mt][nt][d]) * srp[r] * sbl[c])

__device__ __forceinline__ void qstore2(char* __restrict__ Xq8, int r, int c0,
                                        float v0, float v1, float inv) {
    int q0 = __float2int_rn(v0 * inv);
    int q1 = __float2int_rn(v1 * inv);
    int h0 = (q0 + 128) >> 8, l0 = q0 - (h0 << 8);
    int h1 = (q1 + 128) >> 8, l1 = q1 - (h1 << 8);
    int base = r * (XQS * 8) + ((c0 >> 2) << 3) + (c0 & 3);
    *(unsigned short*)(Xq8 + base)     = (unsigned short)((h0 & 0xFF) | ((h1 & 0xFF) << 8));
    *(unsigned short*)(Xq8 + base + 4) = (unsigned short)((l0 & 0xFF) | ((l1 & 0xFF) << 8));
}

__device__ __forceinline__ void quant_epi(float vr[2][4][4], char* __restrict__ Xq8,
                                          float* __restrict__ rmp,
                                          float* __restrict__ srow_out,
                                          float* __restrict__ invs,
                                          int wm, int wn, int lq, int lr, int tid) {
    float rm0[2], rm1[2];
#pragma unroll
    for (int mt = 0; mt < 2; mt++) {
        float m0 = 0.f, m1 = 0.f;
#pragma unroll
        for (int nt = 0; nt < 4; nt++) {
            m0 = fmaxf(m0, fmaxf(vr[mt][nt][0], vr[mt][nt][1]));
            m1 = fmaxf(m1, fmaxf(vr[mt][nt][2], vr[mt][nt][3]));
        }
        m0 = fmaxf(m0, __shfl_xor_sync(0xFFFFFFFFu, m0, 1));
        m0 = fmaxf(m0, __shfl_xor_sync(0xFFFFFFFFu, m0, 2));
        m1 = fmaxf(m1, __shfl_xor_sync(0xFFFFFFFFu, m1, 1));
        m1 = fmaxf(m1, __shfl_xor_sync(0xFFFFFFFFu, m1, 2));
        rm0[mt] = m0; rm1[mt] = m1;
    }
    if (lq == 0) {
#pragma unroll
        for (int mt = 0; mt < 2; mt++) {
            int r0 = wm * 32 + mt * 16 + lr;
            rmp[wn * 64 + r0] = rm0[mt];
            rmp[wn * 64 + r0 + 8] = rm1[mt];
        }
    }
    __syncthreads();
    if (tid < 64) {
        float m = fmaxf(fmaxf(rmp[tid], rmp[64 + tid]),
                        fmaxf(rmp[128 + tid], rmp[192 + tid]));
        m = fmaxf(m, 1e-20f);
        srow_out[tid] = m * (1.f / QMAX);
        invs[tid] = QMAX / m;
    }
    __syncthreads();
#pragma unroll
    for (int mt = 0; mt < 2; mt++)
#pragma unroll
        for (int nt = 0; nt < 4; nt++) {
            int r0 = wm * 32 + mt * 16 + lr;
            int c0 = wn * 32 + nt * 8 + lq * 2;
            qstore2(Xq8, r0, c0,     vr[mt][nt][0], vr[mt][nt][1], invs[r0]);
            qstore2(Xq8, r0 + 8, c0, vr[mt][nt][2], vr[mt][nt][3], invs[r0 + 8]);
        }
}

__device__ __forceinline__ void compose34(float* __restrict__ o,
                                          const float* __restrict__ A,
                                          const float* __restrict__ Bm) {
#pragma unroll
    for (int r = 0; r < 3; r++) {
        float a0 = A[r*4+0], a1 = A[r*4+1], a2 = A[r*4+2], a3 = A[r*4+3];
#pragma unroll
        for (int c = 0; c < 3; c++)
            o[r*4+c] = a0 * Bm[c] + a1 * Bm[4+c] + a2 * Bm[8+c];
        o[r*4+3] = a0 * Bm[3] + a1 * Bm[7] + a2 * Bm[11] + a3;
    }
}

__global__ void __launch_bounds__(256, 2) mlp_kernel(
    const float* __restrict__ act, const float* __restrict__ init_act,
    const float* __restrict__ ba, const float* __restrict__ bi,
    const float* __restrict__ b1, const float* __restrict__ b2,
    const float* __restrict__ ow, const float* __restrict__ ob,
    const int* __restrict__ seq, const float* __restrict__ backb,
    const float* __restrict__ dframes, const int* __restrict__ gidx,
    const float* __restrict__ amask, const float* __restrict__ lit,
    float* __restrict__ out)
{
    extern __shared__ __align__(16) char smem[];
    uint2* Wb0 = (uint2*)(smem + SM_W0);
    uint2* Wb1 = (uint2*)(smem + SM_W1);
    uint2* Xq = (uint2*)(smem + SM_X);
    char*  Xq8 = (char*)(smem + SM_X);
    float* sbs = (float*)(smem + SM_SB);
    float* bias_s = (float*)(smem + SM_BIAS);
    float* srowb = (float*)(smem + SM_SROW);
    float* invs = (float*)(smem + SM_INV);
    float* rmp  = (float*)(smem + SM_RMP);
    float* Un   = (float*)(smem + SM_UNB);       // unnorm, then angles in place
    float* Fs   = (float*)(smem + SM_W1);        // post-L5-gemm alias
    float* saf  = (float*)(smem + SM_W1);        // post-head alias
    float* ows  = (float*)(smem + SM_OWS);

    const int tid = threadIdx.x;
    const int lane = tid & 31;
    const int wid = tid >> 5;
    const int wm = wid >> 2, wn = wid & 3;
    const int lq = lane & 3, lr = lane >> 2;
    const uint32_t w0s = smem_u32(smem) + SM_W0;
    const uint32_t w1s = smem_u32(smem) + SM_W1;

    // ---- one-time staging ----
    copyW_async(w0s, 0, tid); CP_COMMIT();        // pending {L0}
    for (int i = tid; i < 768; i += 256) sbs[i] = sbg[i];
    for (int i = tid; i < 640; i += 256) {
        int slot = i >> 7, c = i & 127;
        float v;
        if (slot == 0)      v = ba[c] + bi[c];
        else if (slot == 1) v = b1[c];
        else if (slot == 2) v = b2[c];
        else if (slot == 3) v = b1[128 + c];
        else                v = b2[128 + c];
        bias_s[i] = v;
    }
    for (int i = tid; i < 1792; i += 256) ows[i] = ow[i];

    int P1[2][4][4], P23[2][4][4];
    float xres[2][4][4];

    // ---- persistent tile loop ----
    for (int tile = blockIdx.x; tile < NTILE; tile += gridDim.x) {
        const int tokBase = tile * 64;

        copyW_async(w1s, 1, tid); CP_COMMIT();     // {L0, L1}
        stageX_quant(Xq, act, tokBase, tid, srowb);
        CP_WAIT(1);                                // L0 resident; {L1}
        __syncthreads();
        zeroP(P1, P23);
        gemm(Wb0, Xq, P1, P23, wm, wn, lane);
        __syncthreads();
        copyW_async(w0s, 2, tid); CP_COMMIT();     // {L1, L2}
        {
            const float* srp = srowb;
            const float* sbl = sbs;
#pragma unroll
            for (int mt = 0; mt < 2; mt++)
#pragma unroll
                for (int nt = 0; nt < 4; nt++) {
                    int r0 = wm * 32 + mt * 16 + lr;
                    int c0 = wn * 32 + nt * 8 + lq * 2;
                    xres[mt][nt][0] = DEQ_VAL(mt, nt, 0, r0, c0);
                    xres[mt][nt][1] = DEQ_VAL(mt, nt, 1, r0, c0 + 1);
                    xres[mt][nt][2] = DEQ_VAL(mt, nt, 2, r0 + 8, c0);
                    xres[mt][nt][3] = DEQ_VAL(mt, nt, 3, r0 + 8, c0 + 1);
                }
        }
        stageX_quant(Xq, init_act, tokBase, tid, srowb + 64);
        CP_WAIT(1);                                // L1 resident; {L2}
        __syncthreads();
        zeroP(P1, P23);
        gemm(Wb1, Xq, P1, P23, wm, wn, lane);
        __syncthreads();
        copyW_async(w1s, 3, tid); CP_COMMIT();     // {L2, L3}
        {
            const float* srp = srowb + 64;
            const float* sbl = sbs + 128;
            float vr[2][4][4];
#pragma unroll
            for (int mt = 0; mt < 2; mt++)
#pragma unroll
                for (int nt = 0; nt < 4; nt++) {
                    int r0 = wm * 32 + mt * 16 + lr;
                    int c0 = wn * 32 + nt * 8 + lq * 2;
                    float bv0 = bias_s[c0], bv1 = bias_s[c0 + 1];
                    xres[mt][nt][0] += DEQ_VAL(mt, nt, 0, r0, c0) + bv0;
                    xres[mt][nt][1] += DEQ_VAL(mt, nt, 1, r0, c0 + 1) + bv1;
                    xres[mt][nt][2] += DEQ_VAL(mt, nt, 2, r0 + 8, c0) + bv0;
                    xres[mt][nt][3] += DEQ_VAL(mt, nt, 3, r0 + 8, c0 + 1) + bv1;
#pragma unroll
                    for (int d = 0; d < 4; d++) vr[mt][nt][d] = fmaxf(xres[mt][nt][d], 0.f);
                }
            quant_epi(vr, Xq8, rmp, srowb, invs, wm, wn, lq, lr, tid);   // x -> buf0
        }

        // ---- resnet blocks; L=2+2blk in b0, L=3+2blk in b1 ----
#pragma unroll 1
        for (int blk = 0; blk < 2; blk++) {
            // w1: h = relu(x@w1 + b1)
            CP_WAIT(1);                            // L(2+2blk) resident
            __syncthreads();
            zeroP(P1, P23);
            gemm(Wb0, Xq, P1, P23, wm, wn, lane);
            __syncthreads();
            // blk0: issue L4 -> b0 ; blk1: issue L0(next tile) -> b0
            copyW_async(w0s, blk == 0 ? 4 : 0, tid); CP_COMMIT();
            {
                const float* srp = srowb;
                const float* sbl = sbs + 128 * (2 + blk * 2);
                const float* bb = bias_s + 128 * (1 + blk * 2);
                float hv[2][4][4];
#pragma unroll
                for (int mt = 0; mt < 2; mt++)
#pragma unroll
                    for (int nt = 0; nt < 4; nt++) {
                        int r0 = wm * 32 + mt * 16 + lr;
                        int c0 = wn * 32 + nt * 8 + lq * 2;
                        float bv0 = bb[c0], bv1 = bb[c0 + 1];
                        hv[mt][nt][0] = fmaxf(DEQ_VAL(mt, nt, 0, r0, c0) + bv0, 0.f);
                        hv[mt][nt][1] = fmaxf(DEQ_VAL(mt, nt, 1, r0, c0 + 1) + bv1, 0.f);
                        hv[mt][nt][2] = fmaxf(DEQ_VAL(mt, nt, 2, r0 + 8, c0) + bv0, 0.f);
                        hv[mt][nt][3] = fmaxf(DEQ_VAL(mt, nt, 3, r0 + 8, c0 + 1) + bv1, 0.f);
                    }
                quant_epi(hv, Xq8, rmp, srowb + 64, invs, wm, wn, lq, lr, tid);  // h -> buf1
            }
            // w2: x += h@w2 + b2
            CP_WAIT(1);                            // L(3+2blk) resident
            __syncthreads();
            zeroP(P1, P23);
            gemm(Wb1, Xq, P1, P23, wm, wn, lane);
            __syncthreads();
            if (blk == 0) { copyW_async(w1s, 5, tid); CP_COMMIT(); }   // {.., L5}
            {
                const float* srp = srowb + 64;
                const float* sbl = sbs + 128 * (3 + blk * 2);
                const float* bb = bias_s + 128 * (2 + blk * 2);
#pragma unroll
                for (int mt = 0; mt < 2; mt++)
#pragma unroll
                    for (int nt = 0; nt < 4; nt++) {
                        int r0 = wm * 32 + mt * 16 + lr;
                        int c0 = wn * 32 + nt * 8 + lq * 2;
                        float bv0 = bb[c0], bv1 = bb[c0 + 1];
                        xres[mt][nt][0] += DEQ_VAL(mt, nt, 0, r0, c0) + bv0;
                        xres[mt][nt][1] += DEQ_VAL(mt, nt, 1, r0, c0 + 1) + bv1;
                        xres[mt][nt][2] += DEQ_VAL(mt, nt, 2, r0 + 8, c0) + bv0;
                        xres[mt][nt][3] += DEQ_VAL(mt, nt, 3, r0 + 8, c0 + 1) + bv1;
                    }
            }
            if (blk == 0) {
                float vr[2][4][4];
#pragma unroll
                for (int mt = 0; mt < 2; mt++)
#pragma unroll
                    for (int nt = 0; nt < 4; nt++)
#pragma unroll
                        for (int d = 0; d < 4; d++) vr[mt][nt][d] = fmaxf(xres[mt][nt][d], 0.f);
                quant_epi(vr, Xq8, rmp, srowb, invs, wm, wn, lq, lr, tid);       // x -> buf0
            } else {
                // final epilogue: Fs lives in b1 region (L5 gemm done)
#pragma unroll
                for (int mt = 0; mt < 2; mt++)
#pragma unroll
                    for (int nt = 0; nt < 4; nt++) {
                        int r0 = wm * 32 + mt * 16 + lr;
                        int c0 = wn * 32 + nt * 8 + lq * 2;
                        Fs[r0 * FS_STRIDE + c0]           = fmaxf(xres[mt][nt][0], 0.f);
                        Fs[r0 * FS_STRIDE + c0 + 1]       = fmaxf(xres[mt][nt][1], 0.f);
                        Fs[(r0 + 8) * FS_STRIDE + c0]     = fmaxf(xres[mt][nt][2], 0.f);
                        Fs[(r0 + 8) * FS_STRIDE + c0 + 1] = fmaxf(xres[mt][nt][3], 0.f);
                    }
            }
        }
        __syncthreads();

        // ---- head: unnorm = relu(x) @ ow + ob ----
        {
            int t = tid & 63, hh = tid >> 6;
            int ch0 = hh * 4;
            int cnt = (hh == 3) ? 2 : 4;
            float a0 = 0.f, a1 = 0.f, a2 = 0.f, a3 = 0.f;
            const float* Xp = Fs + t * FS_STRIDE;
#pragma unroll 4
            for (int k = 0; k < 128; k++) {
                float xv = Xp[k];
                const float* wp = ows + k * 14 + ch0;
                a0 += xv * wp[0];
                a1 += xv * wp[1];
                if (hh != 3) { a2 += xv * wp[2]; a3 += xv * wp[3]; }
            }
            Un[t * 14 + ch0 + 0] = a0 + ob[ch0 + 0];
            Un[t * 14 + ch0 + 1] = a1 + ob[ch0 + 1];
            if (cnt == 4) {
                Un[t * 14 + ch0 + 2] = a2 + ob[ch0 + 2];
                Un[t * 14 + ch0 + 3] = a3 + ob[ch0 + 3];
            }
        }
        __syncthreads();

        // ---- normalize: write unnorm+angles to gmem, angles into Un in place ----
        for (int i = tid; i < 448; i += 256) {
            int t = i & 63, a = i >> 6;
            float sv = Un[t * 14 + 2 * a];
            float cv = Un[t * 14 + 2 * a + 1];
            float inv = rsqrtf(sv * sv + cv * cv + 1e-12f);
            int tok = tokBase + t;
            out[OUT_UN + tok * 14 + 2 * a]      = sv;
            out[OUT_UN + tok * 14 + 2 * a + 1]  = cv;
            float as = sv * inv, ac = cv * inv;
            out[OUT_ANG + tok * 14 + 2 * a]     = as;
            out[OUT_ANG + tok * 14 + 2 * a + 1] = ac;
            Un[t * 14 + 2 * a]     = as;
            Un[t * 14 + 2 * a + 1] = ac;
        }
        __syncthreads();

        // ================= frames + atoms tail (saf in b1 region) =================
        const int g = tid & 7;
        const int tl = tid >> 3;

#pragma unroll
        for (int it = 0; it < 2; it++) {
            int t2 = it * 32 + tl;
            int tok = tokBase + t2;
            int s = seq[tok];
            float sv, cv;
            if (g == 0) { sv = 0.f; cv = 1.f; }
            else {
                sv = Un[t2 * 14 + (g - 1) * 2];
                cv = Un[t2 * 14 + (g - 1) * 2 + 1];
            }
            const float4* df4 = (const float4*)(dframes + (size_t)(s * 8 + g) * 16);
            float* sp = saf + (t2 * 8 + g) * 12;
#pragma unroll
            for (int r = 0; r < 3; r++) {
                float4 m = df4[r];
                sp[r*4+0] = m.x;
                sp[r*4+1] = cv * m.y + sv * m.z;
                sp[r*4+2] = cv * m.z - sv * m.y;
                sp[r*4+3] = m.w;
            }
        }
        __syncthreads();

        if (g == 0) {
#pragma unroll
            for (int it = 0; it < 2; it++) {
                int t2 = it * 32 + tl;
                float* base = saf + t2 * 96;
                float A[12], Bm[12], Cm[12];
#pragma unroll
                for (int i = 0; i < 12; i++) A[i] = base[4 * 12 + i];
#pragma unroll
                for (int i = 0; i < 12; i++) Bm[i] = base[5 * 12 + i];
                compose34(Cm, A, Bm);
#pragma unroll
                for (int i = 0; i < 12; i++) base[5 * 12 + i] = Cm[i];
#pragma unroll
                for (int i = 0; i < 12; i++) Bm[i] = base[6 * 12 + i];
                compose34(A, Cm, Bm);
#pragma unroll
                for (int i = 0; i < 12; i++) base[6 * 12 + i] = A[i];
#pragma unroll
                for (int i = 0; i < 12; i++) Bm[i] = base[7 * 12 + i];
                compose34(Cm, A, Bm);
#pragma unroll
                for (int i = 0; i < 12; i++) base[7 * 12 + i] = Cm[i];
            }
        }
        __syncthreads();

#pragma unroll
        for (int it = 0; it < 2; it++) {
            int t2 = it * 32 + tl;
            int tok = tokBase + t2;
            const float4* bk4 = (const float4*)(backb + (size_t)tok * 16);
            float Bk[12], L[12], G[12];
            float4 b0 = bk4[0], b1v = bk4[1], b2v = bk4[2];
            Bk[0]=b0.x; Bk[1]=b0.y; Bk[2]=b0.z;  Bk[3]=b0.w;
            Bk[4]=b1v.x; Bk[5]=b1v.y; Bk[6]=b1v.z; Bk[7]=b1v.w;
            Bk[8]=b2v.x; Bk[9]=b2v.y; Bk[10]=b2v.z; Bk[11]=b2v.w;
            float* sp = saf + (t2 * 8 + g) * 12;
#pragma unroll
            for (int i = 0; i < 12; i++) L[i] = sp[i];
            compose34(G, Bk, L);
            float* o = out + OUT_ATG + (size_t)tok * 128 + g * 16;
            ((float4*)o)[0] = make_float4(G[0], G[1], G[2], G[3]);
            ((float4*)o)[1] = make_float4(G[4], G[5], G[6], G[7]);
            ((float4*)o)[2] = make_float4(G[8], G[9], G[10], G[11]);
            ((float4*)o)[3] = make_float4(0.f, 0.f, 0.f, 1.f);
#pragma unroll
            for (int i = 0; i < 12; i++) sp[i] = G[i];
        }
        __syncthreads();

        for (int i = tid; i < 896; i += 256) {
            int t2 = i / 14;
            int a = i % 14;
            int tok2 = tokBase + t2;
            int s2 = seq[tok2];
            int idx = s2 * 14 + a;
            int gg = gidx[idx];
            float m = amask[idx];
            float lx = lit[idx*3+0], ly = lit[idx*3+1], lz = lit[idx*3+2];
            const float* Fp = saf + (t2 * 8 + gg) * 12;
            float px = (Fp[0]*lx + Fp[1]*ly + Fp[2]*lz  + Fp[3])  * m;
            float py = (Fp[4]*lx + Fp[5]*ly + Fp[6]*lz  + Fp[7])  * m;
            float pz = (Fp[8]*lx + Fp[9]*ly + Fp[10]*lz + Fp[11]) * m;
            float* po = out + OUT_POS + (size_t)tok2 * 42 + a * 3;
            po[0] = px; po[1] = py; po[2] = pz;
        }
        __syncthreads();   // saf (b1) must be dead before next tile's L1 copy
    }
}

// ---------------------------------------------------------------------------

extern "C" void kernel_launch(void* const* d_in, const int* in_sizes, int n_in,
                              void* d_out, int out_size) {
    const int*   seq      = (const int*)  d_in[0];
    const float* backb    = (const float*)d_in[1];
    const float* act      = (const float*)d_in[2];
    const float* init_act = (const float*)d_in[3];
    const float* Wa       = (const float*)d_in[4];
    const float* ba       = (const float*)d_in[5];
    const float* Wi       = (const float*)d_in[6];
    const float* bi       = (const float*)d_in[7];
    const float* w1       = (const float*)d_in[8];
    const float* b1       = (const float*)d_in[9];
    const float* w2       = (const float*)d_in[10];
    const float* b2       = (const float*)d_in[11];
    const float* ow       = (const float*)d_in[12];
    const float* ob       = (const float*)d_in[13];
    const float* dframes  = (const float*)d_in[14];
    const int*   gidx     = (const int*)  d_in[15];
    const float* amask    = (const float*)d_in[16];
    const float* lit      = (const float*)d_in[17];
    float* out = (float*)d_out;

    cudaFuncSetAttribute(mlp_kernel, cudaFuncAttributeMaxDynamicSharedMemorySize, SM_TOT);

    prep<<<768, 32>>>(Wa, Wi, w1, w2);
    mlp_kernel<<<296, 256, SM_TOT>>>(act, init_act, ba, bi, b1, b2, ow, ob,
                                     seq, backb, dframes, gidx, amask, lit, out);
}

// round 17
// speedup vs baseline: 1.0720x; 1.0720x over previous
#include <cuda_runtime.h>
#include <cstdint>

#define NTOK 65536
#define OUT_ANG 0
#define OUT_UN  (NTOK*14)
#define OUT_POS (2*NTOK*14)
#define OUT_ATG (2*NTOK*14 + NTOK*42)

#define QMAX 32512.f           // 256*127
#define XQS 36                 // row stride in uint2 {h word, l word}
#define LAYER_U2 (128 * XQS)   // 4608 uint2 per W layer image (36864 B)

// smem byte offsets (double-buffered W)
#define SM_W0   0              // 36864 B
#define SM_W1   36864          // 36864 B
#define SM_X    73728          // 18432 B
#define SM_SB   92160          // 3072 B
#define SM_BIAS 95232          // 2560 B
#define SM_SROW 97792          // 512 B
#define SM_INV  98304          // 256 B
#define SM_RMP  98560          // 1024 B
#define SM_UNB  99584          // 3584 B
#define SM_TOT  103168
// post-GEMM aliases:
#define FS_STRIDE 129          // Fs 64x129 fp32 @ 0 (inside W0; final gemm reads W1)
#define SM_OWS  73728          // head weights in dead X region
#define SM_ANG  80896          // angles 64x14 in dead X region

__device__ uint2 wqbuf[6 * LAYER_U2];
__device__ float sbg[6 * 128];

__device__ __forceinline__ void mma_s8(int c[4], uint32_t a0, uint32_t a1,
                                       uint32_t a2, uint32_t a3,
                                       uint32_t b0, uint32_t b1) {
    asm("mma.sync.aligned.m16n8k32.row.col.s32.s8.s8.s32 "
        "{%0,%1,%2,%3}, {%4,%5,%6,%7}, {%8,%9}, {%0,%1,%2,%3};"
        : "+r"(c[0]), "+r"(c[1]), "+r"(c[2]), "+r"(c[3])
        : "r"(a0), "r"(a1), "r"(a2), "r"(a3), "r"(b0), "r"(b1));
}

__device__ __forceinline__ void split4(const int q[4], uint32_t& hw, uint32_t& lw) {
    uint32_t a = 0, b = 0;
#pragma unroll
    for (int i = 0; i < 4; i++) {
        int h = (q[i] + 128) >> 8;
        int l = q[i] - (h << 8);
        a |= (uint32_t)(h & 0xFF) << (8 * i);
        b |= (uint32_t)(l & 0xFF) << (8 * i);
    }
    hw = a; lw = b;
}

__device__ __forceinline__ uint32_t smem_u32(const void* p) {
    uint32_t a; asm("{ .reg .u64 t; cvta.to.shared.u64 t, %1; cvt.u32.u64 %0, t; }" : "=r"(a) : "l"(p));
    return a;
}
#define CP_COMMIT() asm volatile("cp.async.commit_group;" ::: "memory")
#define CP_WAIT(n)  asm volatile("cp.async.wait_group %0;" :: "n"(n) : "memory")

__device__ __forceinline__ void copyW_async(uint32_t dst_s, int layer, int tid) {
    const char* src = (const char*)(wqbuf + (size_t)layer * LAYER_U2);
#pragma unroll
    for (int i = 0; i < 9; i++) {
        uint32_t d = dst_s + (uint32_t)(tid + i * 256) * 16u;
        asm volatile("cp.async.cg.shared.global [%0], [%1], 16;"
                     :: "r"(d), "l"(src + (size_t)(tid + i * 256) * 16) : "memory");
    }
}

// ---------------------------------------------------------------------------
// merged prep: 768 blocks x 32 threads; block = (layer, n) column
// layer order: 0=Wa 1=Wi 2=w1[0] 3=w2[0] 4=w1[1] 5=w2[1]
// ---------------------------------------------------------------------------
__device__ __forceinline__ const float* layer_src(int layer,
    const float* Wa, const float* Wi, const float* w1, const float* w2) {
    switch (layer) {
        case 0: return Wa; case 1: return Wi; case 2: return w1;
        case 3: return w2; case 4: return w1 + 16384; default: return w2 + 16384;
    }
}

__global__ void prep(const float* __restrict__ Wa, const float* __restrict__ Wi,
                     const float* __restrict__ w1, const float* __restrict__ w2) {
    int wgl = blockIdx.x;                    // 0..767
    int layer = wgl >> 7, n = wgl & 127;
    int l = threadIdx.x;                     // word index 0..31
    const float* src = layer_src(layer, Wa, Wi, w1, w2);
    float v[4];
#pragma unroll
    for (int i = 0; i < 4; i++) v[i] = src[(l * 4 + i) * 128 + n];
    float m = fmaxf(fmaxf(fabsf(v[0]), fabsf(v[1])), fmaxf(fabsf(v[2]), fabsf(v[3])));
#pragma unroll
    for (int off = 16; off >= 1; off >>= 1)
        m = fmaxf(m, __shfl_xor_sync(0xFFFFFFFFu, m, off));
    m = fmaxf(m, 1e-20f);
    if (l == 0) sbg[wgl] = m * (1.f / QMAX);
    float inv = QMAX / m;
    int q[4];
#pragma unroll
    for (int i = 0; i < 4; i++) q[i] = __float2int_rn(v[i] * inv);
    uint32_t hw, lw;
    split4(q, hw, lw);
    wqbuf[(size_t)layer * LAYER_U2 + n * XQS + l] = make_uint2(hw, lw);
}

// ---------------------------------------------------------------------------
// fused MLP + frames kernel: 64 tokens/CTA, 256 threads, 2 CTAs/SM (R15 shape)
// ---------------------------------------------------------------------------

__device__ __forceinline__ void stageX_quant(uint2* __restrict__ Xq,
                                             const float* __restrict__ g,
                                             int tokBase, int tid,
                                             float* __restrict__ srow_out) {
    int w = tid >> 5, l = tid & 31;
    const float4* src = (const float4*)g;
#pragma unroll
    for (int i = 0; i < 8; i++) {
        int row = w + 8 * i;
        float4 v = src[(size_t)(tokBase + row) * 32 + l];
        float r0 = fmaxf(v.x, 0.f), r1 = fmaxf(v.y, 0.f);
        float r2 = fmaxf(v.z, 0.f), r3 = fmaxf(v.w, 0.f);
        float lm = fmaxf(fmaxf(r0, r1), fmaxf(r2, r3));
#pragma unroll
        for (int off = 16; off >= 1; off >>= 1)
            lm = fmaxf(lm, __shfl_xor_sync(0xFFFFFFFFu, lm, off));
        lm = fmaxf(lm, 1e-20f);
        float inv = QMAX / lm;
        if (l == 0) srow_out[row] = lm * (1.f / QMAX);
        int q[4] = { __float2int_rn(r0 * inv), __float2int_rn(r1 * inv),
                     __float2int_rn(r2 * inv), __float2int_rn(r3 * inv) };
        uint32_t hw, lw;
        split4(q, hw, lw);
        Xq[row * XQS + l] = make_uint2(hw, lw);
    }
}

__device__ __forceinline__ void zeroP(int P1[2][4][4], int P23[2][4][4]) {
#pragma unroll
    for (int mt = 0; mt < 2; mt++)
#pragma unroll
        for (int nt = 0; nt < 4; nt++)
#pragma unroll
            for (int d = 0; d < 4; d++) { P1[mt][nt][d] = 0; P23[mt][nt][d] = 0; }
}

__device__ __forceinline__ void gemm(const uint2* __restrict__ Wq,
                                     const uint2* __restrict__ Xq,
                                     int P1[2][4][4], int P23[2][4][4],
                                     int wm, int wn, int lane) {
    const int lq = lane & 3, lr = lane >> 2;
#pragma unroll
    for (int kk = 0; kk < 4; kk++) {
        const int p0 = kk * 8 + lq;
        const int p1 = p0 + 4;
        uint32_t a1[2][4], a2[2][4];
#pragma unroll
        for (int mt = 0; mt < 2; mt++) {
            int r = (wm * 32 + mt * 16 + lr) * XQS;
            uint2 v0 = Xq[r + p0];
            uint2 v1 = Xq[r + 8 * XQS + p0];
            uint2 v2 = Xq[r + p1];
            uint2 v3 = Xq[r + 8 * XQS + p1];
            a1[mt][0] = v0.x; a2[mt][0] = v0.y;
            a1[mt][1] = v1.x; a2[mt][1] = v1.y;
            a1[mt][2] = v2.x; a2[mt][2] = v2.y;
            a1[mt][3] = v3.x; a2[mt][3] = v3.y;
        }
#pragma unroll
        for (int nt = 0; nt < 4; nt++) {
            int n = (wn * 32 + nt * 8 + lr) * XQS;
            uint2 b0 = Wq[n + p0];
            uint2 b1 = Wq[n + p1];
#pragma unroll
            for (int mt = 0; mt < 2; mt++) {
                mma_s8(P1[mt][nt],  a1[mt][0], a1[mt][1], a1[mt][2], a1[mt][3], b0.x, b1.x);
                mma_s8(P23[mt][nt], a1[mt][0], a1[mt][1], a1[mt][2], a1[mt][3], b0.y, b1.y);
                mma_s8(P23[mt][nt], a2[mt][0], a2[mt][1], a2[mt][2], a2[mt][3], b0.x, b1.x);
            }
        }
    }
}

#define DEQ_VAL(mt, nt, d, r, c) \
    (fmaf(65536.f, (float)P1[mt][nt][d], 256.f * (float)P23[mt][nt][d]) * srp[r] * sbl[c])

__device__ __forceinline__ void qstore2(char* __restrict__ Xq8, int r, int c0,
                                        float v0, float v1, float inv) {
    int q0 = __float2int_rn(v0 * inv);
    int q1 = __float2int_rn(v1 * inv);
    int h0 = (q0 + 128) >> 8, l0 = q0 - (h0 << 8);
    int h1 = (q1 + 128) >> 8, l1 = q1 - (h1 << 8);
    int base = r * (XQS * 8) + ((c0 >> 2) << 3) + (c0 & 3);
    *(unsigned short*)(Xq8 + base)     = (unsigned short)((h0 & 0xFF) | ((h1 & 0xFF) << 8));
    *(unsigned short*)(Xq8 + base + 4) = (unsigned short)((l0 & 0xFF) | ((l1 & 0xFF) << 8));
}

__device__ __forceinline__ void quant_epi(float vr[2][4][4], char* __restrict__ Xq8,
                                          float* __restrict__ rmp,
                                          float* __restrict__ srow_out,
                                          float* __restrict__ invs,
                                          int wm, int wn, int lq, int lr, int tid) {
    float rm0[2], rm1[2];
#pragma unroll
    for (int mt = 0; mt < 2; mt++) {
        float m0 = 0.f, m1 = 0.f;
#pragma unroll
        for (int nt = 0; nt < 4; nt++) {
            m0 = fmaxf(m0, fmaxf(vr[mt][nt][0], vr[mt][nt][1]));
            m1 = fmaxf(m1, fmaxf(vr[mt][nt][2], vr[mt][nt][3]));
        }
        m0 = fmaxf(m0, __shfl_xor_sync(0xFFFFFFFFu, m0, 1));
        m0 = fmaxf(m0, __shfl_xor_sync(0xFFFFFFFFu, m0, 2));
        m1 = fmaxf(m1, __shfl_xor_sync(0xFFFFFFFFu, m1, 1));
        m1 = fmaxf(m1, __shfl_xor_sync(0xFFFFFFFFu, m1, 2));
        rm0[mt] = m0; rm1[mt] = m1;
    }
    if (lq == 0) {
#pragma unroll
        for (int mt = 0; mt < 2; mt++) {
            int r0 = wm * 32 + mt * 16 + lr;
            rmp[wn * 64 + r0] = rm0[mt];
            rmp[wn * 64 + r0 + 8] = rm1[mt];
        }
    }
    __syncthreads();
    if (tid < 64) {
        float m = fmaxf(fmaxf(rmp[tid], rmp[64 + tid]),
                        fmaxf(rmp[128 + tid], rmp[192 + tid]));
        m = fmaxf(m, 1e-20f);
        srow_out[tid] = m * (1.f / QMAX);
        invs[tid] = QMAX / m;
    }
    __syncthreads();
#pragma unroll
    for (int mt = 0; mt < 2; mt++)
#pragma unroll
        for (int nt = 0; nt < 4; nt++) {
            int r0 = wm * 32 + mt * 16 + lr;
            int c0 = wn * 32 + nt * 8 + lq * 2;
            qstore2(Xq8, r0, c0,     vr[mt][nt][0], vr[mt][nt][1], invs[r0]);
            qstore2(Xq8, r0 + 8, c0, vr[mt][nt][2], vr[mt][nt][3], invs[r0 + 8]);
        }
}

__device__ __forceinline__ void compose34(float* __restrict__ o,
                                          const float* __restrict__ A,
                                          const float* __restrict__ Bm) {
#pragma unroll
    for (int r = 0; r < 3; r++) {
        float a0 = A[r*4+0], a1 = A[r*4+1], a2 = A[r*4+2], a3 = A[r*4+3];
#pragma unroll
        for (int c = 0; c < 3; c++)
            o[r*4+c] = a0 * Bm[c] + a1 * Bm[4+c] + a2 * Bm[8+c];
        o[r*4+3] = a0 * Bm[3] + a1 * Bm[7] + a2 * Bm[11] + a3;
    }
}

__global__ void __launch_bounds__(256, 2) mlp_kernel(
    const float* __restrict__ act, const float* __restrict__ init_act,
    const float* __restrict__ ba, const float* __restrict__ bi,
    const float* __restrict__ b1, const float* __restrict__ b2,
    const float* __restrict__ ow, const float* __restrict__ ob,
    const int* __restrict__ seq, const float* __restrict__ backb,
    const float* __restrict__ dframes, const int* __restrict__ gidx,
    const float* __restrict__ amask, const float* __restrict__ lit,
    float* __restrict__ out)
{
    extern __shared__ __align__(16) char smem[];
    uint2* Wb0 = (uint2*)(smem + SM_W0);
    uint2* Wb1 = (uint2*)(smem + SM_W1);
    uint2* Xq = (uint2*)(smem + SM_X);
    char*  Xq8 = (char*)(smem + SM_X);
    float* sbs = (float*)(smem + SM_SB);
    float* bias_s = (float*)(smem + SM_BIAS);
    float* srowb = (float*)(smem + SM_SROW);
    float* invs = (float*)(smem + SM_INV);
    float* rmp  = (float*)(smem + SM_RMP);
    float* Un   = (float*)(smem + SM_UNB);
    float* Fs   = (float*)smem;
    float* ows  = (float*)(smem + SM_OWS);
    float* angs = (float*)(smem + SM_ANG);
    float* saf  = (float*)smem;

    const int tid = threadIdx.x;
    const int lane = tid & 31;
    const int wid = tid >> 5;
    const int wm = wid >> 2, wn = wid & 3;
    const int lq = lane & 3, lr = lane >> 2;
    const int tokBase = blockIdx.x * 64;
    const uint32_t w0s = smem_u32(smem) + SM_W0;
    const uint32_t w1s = smem_u32(smem) + SM_W1;

    copyW_async(w0s, 0, tid); CP_COMMIT();
    copyW_async(w1s, 1, tid); CP_COMMIT();

    for (int i = tid; i < 768; i += 256) sbs[i] = sbg[i];
    for (int i = tid; i < 640; i += 256) {
        int slot = i >> 7, c = i & 127;
        float v;
        if (slot == 0)      v = ba[c] + bi[c];
        else if (slot == 1) v = b1[c];
        else if (slot == 2) v = b2[c];
        else if (slot == 3) v = b1[128 + c];
        else                v = b2[128 + c];
        bias_s[i] = v;
    }

    int P1[2][4][4], P23[2][4][4];
    float xres[2][4][4];

    // ---- layer 0 (act @ Wa), buffer 0 ----
    stageX_quant(Xq, act, tokBase, tid, srowb);
    CP_WAIT(1);
    __syncthreads();
    zeroP(P1, P23);
    gemm(Wb0, Xq, P1, P23, wm, wn, lane);
    __syncthreads();
    copyW_async(w0s, 2, tid); CP_COMMIT();
    {
        const float* srp = srowb;
        const float* sbl = sbs;
#pragma unroll
        for (int mt = 0; mt < 2; mt++)
#pragma unroll
            for (int nt = 0; nt < 4; nt++) {
                int r0 = wm * 32 + mt * 16 + lr;
                int c0 = wn * 32 + nt * 8 + lq * 2;
                xres[mt][nt][0] = DEQ_VAL(mt, nt, 0, r0, c0);
                xres[mt][nt][1] = DEQ_VAL(mt, nt, 1, r0, c0 + 1);
                xres[mt][nt][2] = DEQ_VAL(mt, nt, 2, r0 + 8, c0);
                xres[mt][nt][3] = DEQ_VAL(mt, nt, 3, r0 + 8, c0 + 1);
            }
    }
    // ---- layer 1 (init @ Wi), buffer 1 ----
    stageX_quant(Xq, init_act, tokBase, tid, srowb + 64);
    CP_WAIT(1);
    __syncthreads();
    zeroP(P1, P23);
    gemm(Wb1, Xq, P1, P23, wm, wn, lane);
    __syncthreads();
    copyW_async(w1s, 3, tid); CP_COMMIT();
    {
        const float* srp = srowb + 64;
        const float* sbl = sbs + 128;
        float vr[2][4][4];
#pragma unroll
        for (int mt = 0; mt < 2; mt++)
#pragma unroll
            for (int nt = 0; nt < 4; nt++) {
                int r0 = wm * 32 + mt * 16 + lr;
                int c0 = wn * 32 + nt * 8 + lq * 2;
                float bv0 = bias_s[c0], bv1 = bias_s[c0 + 1];
                xres[mt][nt][0] += DEQ_VAL(mt, nt, 0, r0, c0) + bv0;
                xres[mt][nt][1] += DEQ_VAL(mt, nt, 1, r0, c0 + 1) + bv1;
                xres[mt][nt][2] += DEQ_VAL(mt, nt, 2, r0 + 8, c0) + bv0;
                xres[mt][nt][3] += DEQ_VAL(mt, nt, 3, r0 + 8, c0 + 1) + bv1;
#pragma unroll
                for (int d = 0; d < 4; d++) vr[mt][nt][d] = fmaxf(xres[mt][nt][d], 0.f);
            }
        quant_epi(vr, Xq8, rmp, srowb, invs, wm, wn, lq, lr, tid);
    }

    // ---- resnet blocks ----
#pragma unroll 1
    for (int blk = 0; blk < 2; blk++) {
        CP_WAIT(1);
        __syncthreads();
        zeroP(P1, P23);
        gemm(Wb0, Xq, P1, P23, wm, wn, lane);
        __syncthreads();
        if (blk == 0) { copyW_async(w0s, 4, tid); CP_COMMIT(); }
        {
            const float* srp = srowb;
            const float* sbl = sbs + 128 * (2 + blk * 2);
            const float* bb = bias_s + 128 * (1 + blk * 2);
            float hv[2][4][4];
#pragma unroll
            for (int mt = 0; mt < 2; mt++)
#pragma unroll
                for (int nt = 0; nt < 4; nt++) {
                    int r0 = wm * 32 + mt * 16 + lr;
                    int c0 = wn * 32 + nt * 8 + lq * 2;
                    float bv0 = bb[c0], bv1 = bb[c0 + 1];
                    hv[mt][nt][0] = fmaxf(DEQ_VAL(mt, nt, 0, r0, c0) + bv0, 0.f);
                    hv[mt][nt][1] = fmaxf(DEQ_VAL(mt, nt, 1, r0, c0 + 1) + bv1, 0.f);
                    hv[mt][nt][2] = fmaxf(DEQ_VAL(mt, nt, 2, r0 + 8, c0) + bv0, 0.f);
                    hv[mt][nt][3] = fmaxf(DEQ_VAL(mt, nt, 3, r0 + 8, c0 + 1) + bv1, 0.f);
                }
            quant_epi(hv, Xq8, rmp, srowb + 64, invs, wm, wn, lq, lr, tid);
        }
        if (blk == 0) { CP_WAIT(1); } else { CP_WAIT(0); }
        __syncthreads();
        zeroP(P1, P23);
        gemm(Wb1, Xq, P1, P23, wm, wn, lane);
        __syncthreads();
        if (blk == 0) { copyW_async(w1s, 5, tid); CP_COMMIT(); }
        {
            const float* srp = srowb + 64;
            const float* sbl = sbs + 128 * (3 + blk * 2);
            const float* bb = bias_s + 128 * (2 + blk * 2);
#pragma unroll
            for (int mt = 0; mt < 2; mt++)
#pragma unroll
                for (int nt = 0; nt < 4; nt++) {
                    int c0 = wn * 32 + nt * 8 + lq * 2;
                    float bv0 = bb[c0], bv1 = bb[c0 + 1];
                    xres[mt][nt][0] += DEQ_VAL(mt, nt, 0, (wm * 32 + mt * 16 + lr), c0) + bv0;
                    xres[mt][nt][1] += DEQ_VAL(mt, nt, 1, (wm * 32 + mt * 16 + lr), c0 + 1) + bv1;
                    xres[mt][nt][2] += DEQ_VAL(mt, nt, 2, (wm * 32 + mt * 16 + lr + 8), c0) + bv0;
                    xres[mt][nt][3] += DEQ_VAL(mt, nt, 3, (wm * 32 + mt * 16 + lr + 8), c0 + 1) + bv1;
                }
        }
        if (blk == 0) {
            float vr[2][4][4];
#pragma unroll
            for (int mt = 0; mt < 2; mt++)
#pragma unroll
                for (int nt = 0; nt < 4; nt++)
#pragma unroll
                    for (int d = 0; d < 4; d++) vr[mt][nt][d] = fmaxf(xres[mt][nt][d], 0.f);
            quant_epi(vr, Xq8, rmp, srowb, invs, wm, wn, lq, lr, tid);
        } else {
#pragma unroll
            for (int mt = 0; mt < 2; mt++)
#pragma unroll
                for (int nt = 0; nt < 4; nt++) {
                    int r0 = wm * 32 + mt * 16 + lr;
                    int c0 = wn * 32 + nt * 8 + lq * 2;
                    Fs[r0 * FS_STRIDE + c0]           = fmaxf(xres[mt][nt][0], 0.f);
                    Fs[r0 * FS_STRIDE + c0 + 1]       = fmaxf(xres[mt][nt][1], 0.f);
                    Fs[(r0 + 8) * FS_STRIDE + c0]     = fmaxf(xres[mt][nt][2], 0.f);
                    Fs[(r0 + 8) * FS_STRIDE + c0 + 1] = fmaxf(xres[mt][nt][3], 0.f);
                }
        }
    }
    for (int i = tid; i < 1792; i += 256) ows[i] = ow[i];
    __syncthreads();

    // ---- head ----
    {
        int t = tid & 63, hh = tid >> 6;
        int ch0 = hh * 4;
        int cnt = (hh == 3) ? 2 : 4;
        float a0 = 0.f, a1 = 0.f, a2 = 0.f, a3 = 0.f;
        const float* Xp = Fs + t * FS_STRIDE;
#pragma unroll 4
        for (int k = 0; k < 128; k++) {
            float xv = Xp[k];
            const float* wp = ows + k * 14 + ch0;
            a0 += xv * wp[0];
            a1 += xv * wp[1];
            if (hh != 3) { a2 += xv * wp[2]; a3 += xv * wp[3]; }
        }
        Un[t * 14 + ch0 + 0] = a0 + ob[ch0 + 0];
        Un[t * 14 + ch0 + 1] = a1 + ob[ch0 + 1];
        if (cnt == 4) {
            Un[t * 14 + ch0 + 2] = a2 + ob[ch0 + 2];
            Un[t * 14 + ch0 + 3] = a3 + ob[ch0 + 3];
        }
    }
    __syncthreads();

    // ---- normalize ----
    for (int i = tid; i < 448; i += 256) {
        int t = i & 63, a = i >> 6;
        float sv = Un[t * 14 + 2 * a];
        float cv = Un[t * 14 + 2 * a + 1];
        float inv = rsqrtf(sv * sv + cv * cv + 1e-12f);
        int tok = tokBase + t;
        out[OUT_UN + tok * 14 + 2 * a]      = sv;
        out[OUT_UN + tok * 14 + 2 * a + 1]  = cv;
        float as = sv * inv, ac = cv * inv;
        out[OUT_ANG + tok * 14 + 2 * a]     = as;
        out[OUT_ANG + tok * 14 + 2 * a + 1] = ac;
        angs[t * 14 + 2 * a]     = as;
        angs[t * 14 + 2 * a + 1] = ac;
    }
    __syncthreads();

    // ================= fused frames + atoms tail =================
    const int g = tid & 7;
    const int tl = tid >> 3;

#pragma unroll
    for (int it = 0; it < 2; it++) {
        int t2 = it * 32 + tl;
        int tok = tokBase + t2;
        int s = seq[tok];
        float sv, cv;
        if (g == 0) { sv = 0.f; cv = 1.f; }
        else {
            sv = angs[t2 * 14 + (g - 1) * 2];
            cv = angs[t2 * 14 + (g - 1) * 2 + 1];
        }
        const float4* df4 = (const float4*)(dframes + (size_t)(s * 8 + g) * 16);
        float* sp = saf + (t2 * 8 + g) * 12;
#pragma unroll
        for (int r = 0; r < 3; r++) {
            float4 m = df4[r];
            sp[r*4+0] = m.x;
            sp[r*4+1] = cv * m.y + sv * m.z;
            sp[r*4+2] = cv * m.z - sv * m.y;
            sp[r*4+3] = m.w;
        }
    }
    __syncthreads();

    if (g == 0) {
#pragma unroll
        for (int it = 0; it < 2; it++) {
            int t2 = it * 32 + tl;
            float* base = saf + t2 * 96;
            float A[12], Bm[12], Cm[12];
#pragma unroll
            for (int i = 0; i < 12; i++) A[i] = base[4 * 12 + i];
#pragma unroll
            for (int i = 0; i < 12; i++) Bm[i] = base[5 * 12 + i];
            compose34(Cm, A, Bm);
#pragma unroll
            for (int i = 0; i < 12; i++) base[5 * 12 + i] = Cm[i];
#pragma unroll
            for (int i = 0; i < 12; i++) Bm[i] = base[6 * 12 + i];
            compose34(A, Cm, Bm);
#pragma unroll
            for (int i = 0; i < 12; i++) base[6 * 12 + i] = A[i];
#pragma unroll
            for (int i = 0; i < 12; i++) Bm[i] = base[7 * 12 + i];
            compose34(Cm, A, Bm);
#pragma unroll
            for (int i = 0; i < 12; i++) base[7 * 12 + i] = Cm[i];
        }
    }
    __syncthreads();

#pragma unroll
    for (int it = 0; it < 2; it++) {
        int t2 = it * 32 + tl;
        int tok = tokBase + t2;
        const float4* bk4 = (const float4*)(backb + (size_t)tok * 16);
        float Bk[12], L[12], G[12];
        float4 b0 = bk4[0], b1v = bk4[1], b2v = bk4[2];
        Bk[0]=b0.x; Bk[1]=b0.y; Bk[2]=b0.z;  Bk[3]=b0.w;
        Bk[4]=b1v.x; Bk[5]=b1v.y; Bk[6]=b1v.z; Bk[7]=b1v.w;
        Bk[8]=b2v.x; Bk[9]=b2v.y; Bk[10]=b2v.z; Bk[11]=b2v.w;
        float* sp = saf + (t2 * 8 + g) * 12;
#pragma unroll
        for (int i = 0; i < 12; i++) L[i] = sp[i];
        compose34(G, Bk, L);
        float* o = out + OUT_ATG + (size_t)tok * 128 + g * 16;
        ((float4*)o)[0] = make_float4(G[0], G[1], G[2], G[3]);
        ((float4*)o)[1] = make_float4(G[4], G[5], G[6], G[7]);
        ((float4*)o)[2] = make_float4(G[8], G[9], G[10], G[11]);
        ((float4*)o)[3] = make_float4(0.f, 0.f, 0.f, 1.f);
#pragma unroll
        for (int i = 0; i < 12; i++) sp[i] = G[i];
    }
    __syncthreads();

    for (int i = tid; i < 896; i += 256) {
        int t2 = i / 14;
        int a = i % 14;
        int tok2 = tokBase + t2;
        int s2 = seq[tok2];
        int idx = s2 * 14 + a;
        int gg = gidx[idx];
        float m = amask[idx];
        float lx = lit[idx*3+0], ly = lit[idx*3+1], lz = lit[idx*3+2];
        const float* Fp = saf + (t2 * 8 + gg) * 12;
        float px = (Fp[0]*lx + Fp[1]*ly + Fp[2]*lz  + Fp[3])  * m;
        float py = (Fp[4]*lx + Fp[5]*ly + Fp[6]*lz  + Fp[7])  * m;
        float pz = (Fp[8]*lx + Fp[9]*ly + Fp[10]*lz + Fp[11]) * m;
        float* po = out + OUT_POS + (size_t)tok2 * 42 + a * 3;
        po[0] = px; po[1] = py; po[2] = pz;
    }
}

// ---------------------------------------------------------------------------

extern "C" void kernel_launch(void* const* d_in, const int* in_sizes, int n_in,
                              void* d_out, int out_size) {
    const int*   seq      = (const int*)  d_in[0];
    const float* backb    = (const float*)d_in[1];
    const float* act      = (const float*)d_in[2];
    const float* init_act = (const float*)d_in[3];
    const float* Wa       = (const float*)d_in[4];
    const float* ba       = (const float*)d_in[5];
    const float* Wi       = (const float*)d_in[6];
    const float* bi       = (const float*)d_in[7];
    const float* w1       = (const float*)d_in[8];
    const float* b1       = (const float*)d_in[9];
    const float* w2       = (const float*)d_in[10];
    const float* b2       = (const float*)d_in[11];
    const float* ow       = (const float*)d_in[12];
    const float* ob       = (const float*)d_in[13];
    const float* dframes  = (const float*)d_in[14];
    const int*   gidx     = (const int*)  d_in[15];
    const float* amask    = (const float*)d_in[16];
    const float* lit      = (const float*)d_in[17];
    float* out = (float*)d_out;

    cudaFuncSetAttribute(mlp_kernel, cudaFuncAttributeMaxDynamicSharedMemorySize, SM_TOT);

    prep<<<768, 32>>>(Wa, Wi, w1, w2);
    mlp_kernel<<<NTOK / 64, 256, SM_TOT>>>(act, init_act, ba, bi, b1, b2, ow, ob,
                                           seq, backb, dframes, gidx, amask, lit, out);
}